// round 12
// baseline (speedup 1.0000x reference)
#include <cuda_runtime.h>

#define CC 64
#define TT 256
#define VV 25
#define NN 128
#define NPOS 819200.0f
#define TOTEL 52428800
#define TPAD 808
#define KSMEM (32 * TPAD * 4)            /* 103424 B */
#define GSMEM ((16384 + 4096 + 128) * 4) /* 82432 B  */
#define HSTR2 33
#define ESMEM ((400 * HSTR2 + 128) * 4)  /* 53312 B  */

typedef unsigned long long ull;

// Device globals (no runtime allocation)
__device__ __align__(16) float g_Wf[VV * CC * CC];  // [v][c][o4][og], o=og*16+o4
__device__ __align__(16) float g_B[CC];
__device__ float g_s[75];
__device__ float g_sum[CC];
__device__ float g_sumsq[CC];
__device__ float g_scale[CC];
__device__ float g_shift[CC];
__device__ float g_xT[TOTEL];   // x transposed: [n][v][c][t]
// hidden blocked: [n][v][tw(16)] tile of 512 ull: og*128 + th*64 + tp*16 + o4,
// each ull = t-pair {t, t+1}, t = tw*16 + th*8 + tp*2
__device__ float g_hid[TOTEL];

__device__ __forceinline__ void ffma2(ull& d, ull a, ull b) {
    asm("fma.rn.f32x2 %0, %1, %2, %0;" : "+l"(d) : "l"(a), "l"(b));
}
__device__ __forceinline__ ull packrep(float v) {
    ull r; asm("mov.b64 %0, {%1,%1};" : "=l"(r) : "f"(v)); return r;
}
__device__ __forceinline__ void unpack2(ull p, float& a, float& b) {
    asm("mov.b64 {%0,%1}, %2;" : "=f"(a), "=f"(b) : "l"(p));
}

// ---------------------------------------------------------------------------
// k0a: softmax rows sum to 1 -> attention collapses to s_i[v] = 1+sum_w(A+GA).
// ---------------------------------------------------------------------------
__global__ void k0a(const float* __restrict__ A, const float* __restrict__ GA,
                    const float* __restrict__ gb) {
    int tid = threadIdx.x;
    if (tid < 75) {
        const float* a = A + tid * 25;
        const float* g = GA + tid * 25;
        float s = 1.f;
        for (int w = 0; w < 25; w++) s += a[w] + g[w];
        g_s[tid] = s;
    }
    if (tid < CC) {
        g_sum[tid] = 0.f;
        g_sumsq[tid] = 0.f;
        float b = 0.f;
        for (int i = 0; i < 3; i++) b += gb[i * CC + tid];
        g_B[tid] = b;
    }
}

// ---------------------------------------------------------------------------
// ktr: transpose x[n][c][t][v] -> xT[n][v][c][t]. Block = (tc of 32 t,
// c-half of 32, n). Reads coalesced float4 into padded smem (16B-aligned
// rows), writes per (v,c) one contiguous 128B float4-run. ~400MB stream.
// ---------------------------------------------------------------------------
__global__ void __launch_bounds__(512, 2) ktr(const float* __restrict__ x) {
    extern __shared__ float ts[];             // [32][TPAD]
    int tid = threadIdx.x;
    int tc = blockIdx.x >> 1, ch = blockIdx.x & 1;
    int n = blockIdx.y;

    const float4* src4 =
        (const float4*)(x + (size_t)n * 409600 + (size_t)ch * 32 * 6400 + tc * 800);
    for (int e = tid; e < 6400; e += 512) {
        int c = e / 200, q = e - c * 200;
        ((float4*)(ts + c * TPAD))[q] = src4[c * 1600 + q];
    }
    __syncthreads();

    float4* dst4 = (float4*)g_xT;
    for (int e = tid; e < 6400; e += 512) {
        int t4 = e & 7;
        int cv = e >> 3;                      // c*25 + v
        int c = cv / 25, v = cv - c * 25;
        const float* p = ts + c * TPAD + t4 * 100 + v;
        float4 f;
        f.x = p[0]; f.y = p[25]; f.z = p[50]; f.w = p[75];
        dst4[(((size_t)n * 25 + v) * 64 + ch * 32 + c) * 64 + tc * 8 + t4] = f;
    }
}

// ---------------------------------------------------------------------------
// k0b: folded weights g_Wf[((v*64+c)*16+o4)*4+og] = sum_i s_i[v]*gw[i][o][c].
// ---------------------------------------------------------------------------
__global__ void k0b(const float* __restrict__ gw) {
    __shared__ float s_sh[75];
    int tid = threadIdx.x;
    if (tid < 75) s_sh[tid] = g_s[tid];
    __syncthreads();
    for (int idx = blockIdx.x * blockDim.x + tid; idx < VV * CC * CC;
         idx += gridDim.x * blockDim.x) {
        int og = idx & 3;
        int o4 = (idx >> 2) & 15;
        int c = (idx >> 6) & 63;
        int v = idx >> 12;
        int o = og * 16 + o4;
        float w = 0.f;
        for (int i = 0; i < 3; i++)
            w += s_sh[i * 25 + v] * gw[(i * CC + o) * CC + c];
        g_Wf[idx] = w;
    }
}

// ---------------------------------------------------------------------------
// gemmst: block = (v, n). 512 thr = 16 warps, occupancy 2 (8 warps/SMSP).
// Stage ONCE into smem: x slice xT[n][v] (64KB, plain memcpy) + weight
// slice g_Wf[v] (16KB, plain memcpy). Warp = t-chunk tw (16 t); lane =
// (o4, th). Mainloop per channel: 1 LDS.128 weights + 2 LDS.128 x (t-pairs)
// + 16 FFMA2 — no global loads. acc = 4og x 4tp packed f32x2 (32 regs).
// Stats via smem atomics -> global; hidden stored blocked from registers.
// ---------------------------------------------------------------------------
__global__ void __launch_bounds__(512, 2) gemmst(int unused) {
    extern __shared__ float smem[];
    float* xv = smem;                // [64][256]
    float* ws = smem + 16384;        // [64][16][4]
    float* aux = smem + 20480;       // stats[128]
    int tid = threadIdx.x;
    int v = blockIdx.x, n = blockIdx.y;

    if (tid < 128) aux[tid] = 0.f;
    {
        const float4* s4 = (const float4*)(g_xT + ((size_t)n * 25 + v) * 16384);
        float4* d4 = (float4*)xv;
#pragma unroll
        for (int e = 0; e < 8; e++) d4[tid + e * 512] = s4[tid + e * 512];
        const float4* w4 = (const float4*)(g_Wf + (size_t)v * 4096);
        float4* dw = (float4*)ws;
#pragma unroll
        for (int e = 0; e < 2; e++) dw[tid + e * 512] = w4[tid + e * 512];
    }
    __syncthreads();

    int tw = tid >> 5, lane = tid & 31;
    int o4 = lane & 15, th = lane >> 4;

    ull acc[4][4];                   // [og][tp]
#pragma unroll
    for (int og = 0; og < 4; og++) {
        ull b = packrep(g_B[og * 16 + o4]);
#pragma unroll
        for (int tp = 0; tp < 4; tp++) acc[og][tp] = b;
    }

    const float4* wp = (const float4*)ws + o4;                     // + c*16
    const ulonglong2* xp = (const ulonglong2*)xv + tw * 4 + th * 2; // + c*64

#pragma unroll 4
    for (int c = 0; c < CC; c++) {
        float4 w = wp[c * 16];
        ulonglong2 xa = xp[c * 64];
        ulonglong2 xb = xp[c * 64 + 1];
        ull w0 = packrep(w.x), w1 = packrep(w.y);
        ull w2 = packrep(w.z), w3 = packrep(w.w);
        ffma2(acc[0][0], w0, xa.x); ffma2(acc[1][0], w1, xa.x);
        ffma2(acc[2][0], w2, xa.x); ffma2(acc[3][0], w3, xa.x);
        ffma2(acc[0][1], w0, xa.y); ffma2(acc[1][1], w1, xa.y);
        ffma2(acc[2][1], w2, xa.y); ffma2(acc[3][1], w3, xa.y);
        ffma2(acc[0][2], w0, xb.x); ffma2(acc[1][2], w1, xb.x);
        ffma2(acc[2][2], w2, xb.x); ffma2(acc[3][2], w3, xb.x);
        ffma2(acc[0][3], w0, xb.y); ffma2(acc[1][3], w1, xb.y);
        ffma2(acc[2][3], w2, xb.y); ffma2(acc[3][3], w3, xb.y);
    }

    // stats (each (o,t) counted once per v-block -> grid-wide exact)
#pragma unroll
    for (int og = 0; og < 4; og++) {
        int o = og * 16 + o4;
        float s = 0.f, q = 0.f;
#pragma unroll
        for (int tp = 0; tp < 4; tp++) {
            float h0, h1;
            unpack2(acc[og][tp], h0, h1);
            s += h0 + h1;
            q += h0 * h0 + h1 * h1;
        }
        atomicAdd(&aux[o], s);
        atomicAdd(&aux[64 + o], q);
    }

    // blocked hidden store
    ull* dst = (ull*)g_hid + (((size_t)n * 25 + v) * 16 + tw) * 512 + th * 64 + o4;
#pragma unroll
    for (int og = 0; og < 4; og++)
#pragma unroll
        for (int tp = 0; tp < 4; tp++)
            dst[og * 128 + tp * 16] = acc[og][tp];

    __syncthreads();
    if (tid < 64) atomicAdd(&g_sum[tid], aux[tid]);
    else if (tid < 128) atomicAdd(&g_sumsq[tid - 64], aux[tid]);
}

// ---------------------------------------------------------------------------
// kbn: training-mode biased-var BN folded to per-channel scale/shift.
// ---------------------------------------------------------------------------
__global__ void kbn(const float* __restrict__ gamma, const float* __restrict__ beta) {
    int o = threadIdx.x;
    if (o < CC) {
        float m = g_sum[o] * (1.0f / NPOS);
        float var = g_sumsq[o] * (1.0f / NPOS) - m * m;
        float r = rsqrtf(var + 1e-5f);
        float sc = gamma[o] * r;
        g_scale[o] = sc;
        g_shift[o] = beta[o] - m * sc;
    }
}

// ---------------------------------------------------------------------------
// epi: block = (tw, o-half, n): 16 t x 32 o x 25 v. Phase 1: read blocked
// hid (per v one contiguous 1KB run), decode into hsm[pos][33]. Phase 2:
// out = relu(hid*scale+shift + x), fully coalesced. occ 4.
// ---------------------------------------------------------------------------
__global__ void __launch_bounds__(512, 4) epi(const float* __restrict__ x,
                                              float* __restrict__ out) {
    extern __shared__ float hsm[];            // [400][33]
    float* sc_sh = hsm + 400 * HSTR2;
    float* sf_sh = sc_sh + 64;
    int tid = threadIdx.x;
    int tw = blockIdx.x >> 1, h = blockIdx.x & 1;
    int n = blockIdx.y;

    if (tid < 64) { sc_sh[tid] = g_scale[tid]; sf_sh[tid] = g_shift[tid]; }

    const float4* hb = (const float4*)g_hid;
#pragma unroll 2
    for (int i = tid; i < 3200; i += 512) {
        int v = i >> 7, r4 = i & 127;
        float4 f = hb[(((size_t)n * 25 + v) * 16 + tw) * 256 + h * 128 + r4];
        int og_l = r4 >> 6;
        int r = r4 & 63;
        int o4e = (r & 7) * 2;
        int tp = (r >> 3) & 3;
        int th = r >> 5;
        int ol = og_l * 16 + o4e;
        int pos = (th * 8 + tp * 2) * 25 + v;
        float* p = hsm + pos * HSTR2 + ol;
        p[0] = f.x;                           // (ol,   t)
        p[25 * HSTR2] = f.y;                  // (ol,   t+1)
        p[1] = f.z;                           // (ol+1, t)
        p[25 * HSTR2 + 1] = f.w;              // (ol+1, t+1)
    }
    __syncthreads();

    if (tid < 400) {
        size_t base = (size_t)n * 409600 + (size_t)h * 32 * 6400 + tw * 400 + tid;
        const float* xp = x + base;
        float* op = out + base;
        const float* hrow = hsm + tid * HSTR2;
#pragma unroll 8
        for (int cl = 0; cl < 32; cl++) {
            int c = h * 32 + cl;
            float val = fmaf(hrow[cl], sc_sh[c], sf_sh[c]) + xp[cl * 6400];
            op[cl * 6400] = fmaxf(val, 0.f);
        }
    }
}

extern "C" void kernel_launch(void* const* d_in, const int* in_sizes, int n_in,
                              void* d_out, int out_size) {
    const float* x     = (const float*)d_in[0];
    const float* A     = (const float*)d_in[1];
    const float* GA    = (const float*)d_in[2];
    const float* gw    = (const float*)d_in[7];
    const float* gb    = (const float*)d_in[8];
    const float* gamma = (const float*)d_in[9];
    const float* beta  = (const float*)d_in[10];
    float* out = (float*)d_out;
    (void)in_sizes; (void)n_in; (void)out_size;

    cudaFuncSetAttribute(ktr, cudaFuncAttributeMaxDynamicSharedMemorySize, KSMEM);
    cudaFuncSetAttribute(gemmst, cudaFuncAttributeMaxDynamicSharedMemorySize, GSMEM);
    cudaFuncSetAttribute(epi, cudaFuncAttributeMaxDynamicSharedMemorySize, ESMEM);

    k0a<<<1, 128>>>(A, GA, gb);                       // idx 0
    ktr<<<dim3(16, NN), 512, KSMEM>>>(x);             // idx 1
    k0b<<<52, 256>>>(gw);                             // idx 2
    gemmst<<<dim3(VV, NN), 512, GSMEM>>>(0);          // idx 3 -> ncu capture
    kbn<<<1, 64>>>(gamma, beta);                      // idx 4
    epi<<<dim3(32, NN), 512, ESMEM>>>(x, out);        // idx 5
}

// round 13
// speedup vs baseline: 1.0876x; 1.0876x over previous
#include <cuda_runtime.h>
#include <cuda_fp16.h>

#define CC 64
#define TT 256
#define VV 25
#define NN 128
#define NPOS 819200.0f
#define TOTEL 52428800
#define KROW 408                         /* 16t*25v + 8 pad */
#define KSMEM (32 * KROW * 4)            /* 52224 B -> occ 4 */
#define GSMEM ((16384 + 4096 + 128) * 4) /* 82432 B  */
#define HSTR2 33
#define ESMEM ((400 * HSTR2 + 128) * 4)  /* 53312 B  */

typedef unsigned long long ull;

// Device globals (no runtime allocation)
__device__ __align__(16) float g_Wf[VV * CC * CC];  // [v][c][o4][og], o=og*16+o4
__device__ __align__(16) float g_B[CC];
__device__ float g_s[75];
__device__ float g_sum[CC];
__device__ float g_sumsq[CC];
__device__ float g_scale[CC];
__device__ float g_shift[CC];
__device__ float g_xT[TOTEL];            // x transposed: [n][v][c][t]
// hidden fp16: blocked [n][v][tw(16)] tile of 512 half2 (u32):
// u32 idx = og*128 + th*64 + tp*16 + o4; half2 = t-pair {t, t+1}
__device__ __half2 g_hidh[TOTEL / 2];

__device__ __forceinline__ void ffma2(ull& d, ull a, ull b) {
    asm("fma.rn.f32x2 %0, %1, %2, %0;" : "+l"(d) : "l"(a), "l"(b));
}
__device__ __forceinline__ ull packrep(float v) {
    ull r; asm("mov.b64 %0, {%1,%1};" : "=l"(r) : "f"(v)); return r;
}
__device__ __forceinline__ void unpack2(ull p, float& a, float& b) {
    asm("mov.b64 {%0,%1}, %2;" : "=f"(a), "=f"(b) : "l"(p));
}

// ---------------------------------------------------------------------------
// k0a: softmax rows sum to 1 -> attention collapses to s_i[v] = 1+sum_w(A+GA).
// ---------------------------------------------------------------------------
__global__ void k0a(const float* __restrict__ A, const float* __restrict__ GA,
                    const float* __restrict__ gb) {
    int tid = threadIdx.x;
    if (tid < 75) {
        const float* a = A + tid * 25;
        const float* g = GA + tid * 25;
        float s = 1.f;
        for (int w = 0; w < 25; w++) s += a[w] + g[w];
        g_s[tid] = s;
    }
    if (tid < CC) {
        g_sum[tid] = 0.f;
        g_sumsq[tid] = 0.f;
        float b = 0.f;
        for (int i = 0; i < 3; i++) b += gb[i * CC + tid];
        g_B[tid] = b;
    }
}

// ---------------------------------------------------------------------------
// ktr: transpose x[n][c][t][v] -> xT[n][v][c][t]. Tile = 16t x 32c x 25v
// (52 KB smem -> occupancy 4, 4096 blocks: DRAM-stream bound).
// Reads coalesced float4; writes 64B runs per (v,c).
// ---------------------------------------------------------------------------
__global__ void __launch_bounds__(512, 4) ktr(const float* __restrict__ x) {
    extern __shared__ float ts[];             // [32c][KROW]
    int tid = threadIdx.x;
    int tc = blockIdx.x >> 1, ch = blockIdx.x & 1;
    int n = blockIdx.y;

    const float4* src4 =
        (const float4*)(x + (size_t)n * 409600 + (size_t)ch * 32 * 6400 + tc * 400);
    for (int e = tid; e < 3200; e += 512) {
        int c = e / 100, q = e - c * 100;
        ((float4*)(ts + c * KROW))[q] = src4[c * 1600 + q];
    }
    __syncthreads();

    float4* dst4 = (float4*)g_xT;
    for (int e = tid; e < 3200; e += 512) {
        int t4 = e & 3;
        int cv = e >> 2;                      // c*25 + v
        int c = cv / 25, v = cv - c * 25;
        const float* p = ts + c * KROW + t4 * 100 + v;
        float4 f;
        f.x = p[0]; f.y = p[25]; f.z = p[50]; f.w = p[75];
        dst4[(((size_t)n * 25 + v) * 64 + ch * 32 + c) * 64 + tc * 4 + t4] = f;
    }
}

// ---------------------------------------------------------------------------
// k0b: folded weights g_Wf[((v*64+c)*16+o4)*4+og] = sum_i s_i[v]*gw[i][o][c].
// ---------------------------------------------------------------------------
__global__ void k0b(const float* __restrict__ gw) {
    __shared__ float s_sh[75];
    int tid = threadIdx.x;
    if (tid < 75) s_sh[tid] = g_s[tid];
    __syncthreads();
    for (int idx = blockIdx.x * blockDim.x + tid; idx < VV * CC * CC;
         idx += gridDim.x * blockDim.x) {
        int og = idx & 3;
        int o4 = (idx >> 2) & 15;
        int c = (idx >> 6) & 63;
        int v = idx >> 12;
        int o = og * 16 + o4;
        float w = 0.f;
        for (int i = 0; i < 3; i++)
            w += s_sh[i * 25 + v] * gw[(i * CC + o) * CC + c];
        g_Wf[idx] = w;
    }
}

// ---------------------------------------------------------------------------
// gemmst: block = (v, n). 512 thr = 16 warps, occupancy 2 (8 warps/SMSP).
// Stage ONCE into smem: x slice xT[n][v] (64KB) + weight slice (16KB), both
// plain coalesced memcpys. Warp = t-chunk tw (16 t); lane = (o4, th).
// Mainloop per channel: 1 LDS.128 weights + 2 LDS.128 x + 16 FFMA2, no
// global loads. Stats fp32-exact via smem atomics; hidden stored fp16
// (half2 per t-pair) in blocked layout.
// ---------------------------------------------------------------------------
__global__ void __launch_bounds__(512, 2) gemmst(int unused) {
    extern __shared__ float smem[];
    float* xv = smem;                // [64][256]
    float* ws = smem + 16384;        // [64][16][4]
    float* aux = smem + 20480;       // stats[128]
    int tid = threadIdx.x;
    int v = blockIdx.x, n = blockIdx.y;

    if (tid < 128) aux[tid] = 0.f;
    {
        const float4* s4 = (const float4*)(g_xT + ((size_t)n * 25 + v) * 16384);
        float4* d4 = (float4*)xv;
#pragma unroll
        for (int e = 0; e < 8; e++) d4[tid + e * 512] = s4[tid + e * 512];
        const float4* w4 = (const float4*)(g_Wf + (size_t)v * 4096);
        float4* dw = (float4*)ws;
#pragma unroll
        for (int e = 0; e < 2; e++) dw[tid + e * 512] = w4[tid + e * 512];
    }
    __syncthreads();

    int tw = tid >> 5, lane = tid & 31;
    int o4 = lane & 15, th = lane >> 4;

    ull acc[4][4];                   // [og][tp]
#pragma unroll
    for (int og = 0; og < 4; og++) {
        ull b = packrep(g_B[og * 16 + o4]);
#pragma unroll
        for (int tp = 0; tp < 4; tp++) acc[og][tp] = b;
    }

    const float4* wp = (const float4*)ws + o4;                      // + c*16
    const ulonglong2* xp = (const ulonglong2*)xv + tw * 4 + th * 2; // + c*64

#pragma unroll 4
    for (int c = 0; c < CC; c++) {
        float4 w = wp[c * 16];
        ulonglong2 xa = xp[c * 64];
        ulonglong2 xb = xp[c * 64 + 1];
        ull w0 = packrep(w.x), w1 = packrep(w.y);
        ull w2 = packrep(w.z), w3 = packrep(w.w);
        ffma2(acc[0][0], w0, xa.x); ffma2(acc[1][0], w1, xa.x);
        ffma2(acc[2][0], w2, xa.x); ffma2(acc[3][0], w3, xa.x);
        ffma2(acc[0][1], w0, xa.y); ffma2(acc[1][1], w1, xa.y);
        ffma2(acc[2][1], w2, xa.y); ffma2(acc[3][1], w3, xa.y);
        ffma2(acc[0][2], w0, xb.x); ffma2(acc[1][2], w1, xb.x);
        ffma2(acc[2][2], w2, xb.x); ffma2(acc[3][2], w3, xb.x);
        ffma2(acc[0][3], w0, xb.y); ffma2(acc[1][3], w1, xb.y);
        ffma2(acc[2][3], w2, xb.y); ffma2(acc[3][3], w3, xb.y);
    }

    // stats (fp32 exact) + fp16 blocked hidden store
    unsigned* dst = (unsigned*)g_hidh
                    + (((size_t)n * 25 + v) * 16 + tw) * 512 + th * 64 + o4;
#pragma unroll
    for (int og = 0; og < 4; og++) {
        int o = og * 16 + o4;
        float s = 0.f, q = 0.f;
#pragma unroll
        for (int tp = 0; tp < 4; tp++) {
            float h0, h1;
            unpack2(acc[og][tp], h0, h1);
            s += h0 + h1;
            q += h0 * h0 + h1 * h1;
            __half2 hh = __floats2half2_rn(h0, h1);
            dst[og * 128 + tp * 16] = *(unsigned*)&hh;
        }
        atomicAdd(&aux[o], s);
        atomicAdd(&aux[64 + o], q);
    }

    __syncthreads();
    if (tid < 64) atomicAdd(&g_sum[tid], aux[tid]);
    else if (tid < 128) atomicAdd(&g_sumsq[tid - 64], aux[tid]);
}

// ---------------------------------------------------------------------------
// kbn: training-mode biased-var BN folded to per-channel scale/shift.
// ---------------------------------------------------------------------------
__global__ void kbn(const float* __restrict__ gamma, const float* __restrict__ beta) {
    int o = threadIdx.x;
    if (o < CC) {
        float m = g_sum[o] * (1.0f / NPOS);
        float var = g_sumsq[o] * (1.0f / NPOS) - m * m;
        float r = rsqrtf(var + 1e-5f);
        float sc = gamma[o] * r;
        g_scale[o] = sc;
        g_shift[o] = beta[o] - m * sc;
    }
}

// ---------------------------------------------------------------------------
// epi: block = (tw, o-half, n). Phase 1: read blocked fp16 hid (uint2 = 2
// half2 = old float4 index space), decode into hsm[pos][33]. Phase 2:
// out = relu(hid*scale+shift + x), fully coalesced. occ 4.
// ---------------------------------------------------------------------------
__global__ void __launch_bounds__(512, 4) epi(const float* __restrict__ x,
                                              float* __restrict__ out) {
    extern __shared__ float hsm[];            // [400][33]
    float* sc_sh = hsm + 400 * HSTR2;
    float* sf_sh = sc_sh + 64;
    int tid = threadIdx.x;
    int tw = blockIdx.x >> 1, h = blockIdx.x & 1;
    int n = blockIdx.y;

    if (tid < 64) { sc_sh[tid] = g_scale[tid]; sf_sh[tid] = g_shift[tid]; }

    const uint2* hb = (const uint2*)g_hidh;
#pragma unroll 2
    for (int i = tid; i < 3200; i += 512) {
        int v = i >> 7, r4 = i & 127;
        uint2 f = hb[(((size_t)n * 25 + v) * 16 + tw) * 256 + h * 128 + r4];
        float2 a = __half22float2(*(const __half2*)&f.x);
        float2 b = __half22float2(*(const __half2*)&f.y);
        int og_l = r4 >> 6;
        int r = r4 & 63;
        int o4e = (r & 7) * 2;
        int tp = (r >> 3) & 3;
        int th = r >> 5;
        int ol = og_l * 16 + o4e;
        int pos = (th * 8 + tp * 2) * 25 + v;
        float* p = hsm + pos * HSTR2 + ol;
        p[0] = a.x;                           // (ol,   t)
        p[25 * HSTR2] = a.y;                  // (ol,   t+1)
        p[1] = b.x;                           // (ol+1, t)
        p[25 * HSTR2 + 1] = b.y;              // (ol+1, t+1)
    }
    __syncthreads();

    if (tid < 400) {
        size_t base = (size_t)n * 409600 + (size_t)h * 32 * 6400 + tw * 400 + tid;
        const float* xp = x + base;
        float* op = out + base;
        const float* hrow = hsm + tid * HSTR2;
#pragma unroll 8
        for (int cl = 0; cl < 32; cl++) {
            int c = h * 32 + cl;
            float val = fmaf(hrow[cl], sc_sh[c], sf_sh[c]) + xp[cl * 6400];
            op[cl * 6400] = fmaxf(val, 0.f);
        }
    }
}

extern "C" void kernel_launch(void* const* d_in, const int* in_sizes, int n_in,
                              void* d_out, int out_size) {
    const float* x     = (const float*)d_in[0];
    const float* A     = (const float*)d_in[1];
    const float* GA    = (const float*)d_in[2];
    const float* gw    = (const float*)d_in[7];
    const float* gb    = (const float*)d_in[8];
    const float* gamma = (const float*)d_in[9];
    const float* beta  = (const float*)d_in[10];
    float* out = (float*)d_out;
    (void)in_sizes; (void)n_in; (void)out_size;

    cudaFuncSetAttribute(ktr, cudaFuncAttributeMaxDynamicSharedMemorySize, KSMEM);
    cudaFuncSetAttribute(gemmst, cudaFuncAttributeMaxDynamicSharedMemorySize, GSMEM);
    cudaFuncSetAttribute(epi, cudaFuncAttributeMaxDynamicSharedMemorySize, ESMEM);

    k0a<<<1, 128>>>(A, GA, gb);                       // idx 0
    ktr<<<dim3(32, NN), 512, KSMEM>>>(x);             // idx 1
    k0b<<<52, 256>>>(gw);                             // idx 2
    gemmst<<<dim3(VV, NN), 512, GSMEM>>>(0);          // idx 3 -> ncu capture
    kbn<<<1, 64>>>(gamma, beta);                      // idx 4
    epi<<<dim3(32, NN), 512, ESMEM>>>(x, out);        // idx 5
}

// round 14
// speedup vs baseline: 1.1393x; 1.0476x over previous
#include <cuda_runtime.h>
#include <cuda_fp16.h>

#define CC 64
#define TT 256
#define VV 25
#define NN 128
#define NPOS 819200.0f
#define TOTEL 52428800
#define KSMEM (2 * 12800 * 4)            /* double-buffered 50KB tiles */
#define GSMEM ((16384 + 4096 + 128) * 4) /* 82432 B  */
#define HSTR2 33
#define ESMEM ((400 * HSTR2 + 128) * 4)  /* 53312 B  */

typedef unsigned long long ull;

// Device globals (no runtime allocation)
__device__ __align__(16) float g_Wf[VV * CC * CC];  // [v][c][o4][og], o=og*16+o4
__device__ __align__(16) float g_B[CC];
__device__ float g_s[75];
__device__ float g_sum[CC];
__device__ float g_sumsq[CC];
__device__ float g_scale[CC];
__device__ float g_shift[CC];
__device__ float g_xT[TOTEL];            // x transposed: [n][v][c][t]
// hidden fp16: blocked [n][v][tw(16)] tile of 512 half2 (u32):
// u32 idx = og*128 + th*64 + tp*16 + o4; half2 = t-pair {t, t+1}
__device__ __half2 g_hidh[TOTEL / 2];

__device__ __forceinline__ void ffma2(ull& d, ull a, ull b) {
    asm("fma.rn.f32x2 %0, %1, %2, %0;" : "+l"(d) : "l"(a), "l"(b));
}
__device__ __forceinline__ ull packrep(float v) {
    ull r; asm("mov.b64 %0, {%1,%1};" : "=l"(r) : "f"(v)); return r;
}
__device__ __forceinline__ void unpack2(ull p, float& a, float& b) {
    asm("mov.b64 {%0,%1}, %2;" : "=f"(a), "=f"(b) : "l"(p));
}

// ---------------------------------------------------------------------------
// k0a: softmax rows sum to 1 -> attention collapses to s_i[v] = 1+sum_w(A+GA).
// ---------------------------------------------------------------------------
__global__ void k0a(const float* __restrict__ A, const float* __restrict__ GA,
                    const float* __restrict__ gb) {
    int tid = threadIdx.x;
    if (tid < 75) {
        const float* a = A + tid * 25;
        const float* g = GA + tid * 25;
        float s = 1.f;
        for (int w = 0; w < 25; w++) s += a[w] + g[w];
        g_s[tid] = s;
    }
    if (tid < CC) {
        g_sum[tid] = 0.f;
        g_sumsq[tid] = 0.f;
        float b = 0.f;
        for (int i = 0; i < 3; i++) b += gb[i * CC + tid];
        g_B[tid] = b;
    }
}

// ---------------------------------------------------------------------------
// ktr: transpose x[n][c][t][v] -> xT[n][v][c][t], PIPELINED.
// 1024 blocks = (n, grp of 4 tiles); tile = 32c x 16t x 25v = 50KB.
// Double-buffered cp.async.cg (no reg roundtrip): stage tile i+1 while the
// LDS-gather/STG phase of tile i runs -> DRAM latency hidden, bubbles
// amortized over 4 tiles. src/dst of cp.async both linear (rows of a tile
// are contiguous 400-float runs in x; smem dst byte = e*16).
// ---------------------------------------------------------------------------
__global__ void __launch_bounds__(512, 2) ktr(const float* __restrict__ x) {
    extern __shared__ float buf[];            // 2 x 12800 floats
    int tid = threadIdx.x;
    int n = blockIdx.x >> 3;
    int grp = blockIdx.x & 7;                 // tiles grp*4 .. grp*4+3

    auto stage = [&](int tile, int b) {
        int ch = tile >> 4, tt = tile & 15;   // c-half, t-chunk
        const char* src = (const char*)(x + (size_t)n * 409600
                                        + (size_t)ch * 32 * 6400 + tt * 400);
        unsigned dbase = (unsigned)__cvta_generic_to_shared(buf + b * 12800);
        for (int e = tid; e < 3200; e += 512) {
            int c = e / 100, q = e - c * 100;
            asm volatile("cp.async.cg.shared.global [%0], [%1], 16;"
                         :: "r"(dbase + (unsigned)e * 16),
                            "l"(src + (size_t)c * 25600 + q * 16));
        }
        asm volatile("cp.async.commit_group;");
    };

    stage(grp * 4, 0);
    float4* dst4 = (float4*)g_xT;
#pragma unroll 1
    for (int i = 0; i < 4; i++) {
        int tile = grp * 4 + i;
        if (i < 3) {
            stage(tile + 1, (i + 1) & 1);
            asm volatile("cp.async.wait_group 1;");
        } else {
            asm volatile("cp.async.wait_group 0;");
        }
        __syncthreads();
        const float* tb = buf + (i & 1) * 12800;
        int ch = tile >> 4, tt = tile & 15;
        for (int e = tid; e < 3200; e += 512) {
            int t4g = e & 3, cv = e >> 2;
            int c = cv / 25, v = cv - c * 25;
            const float* p = tb + c * 400 + t4g * 100 + v;
            float4 f;
            f.x = p[0]; f.y = p[25]; f.z = p[50]; f.w = p[75];
            dst4[(((size_t)n * 25 + v) * 64 + ch * 32 + c) * 64 + tt * 4 + t4g] = f;
        }
        __syncthreads();
    }
}

// ---------------------------------------------------------------------------
// k0b: folded weights g_Wf[((v*64+c)*16+o4)*4+og] = sum_i s_i[v]*gw[i][o][c].
// ---------------------------------------------------------------------------
__global__ void k0b(const float* __restrict__ gw) {
    __shared__ float s_sh[75];
    int tid = threadIdx.x;
    if (tid < 75) s_sh[tid] = g_s[tid];
    __syncthreads();
    for (int idx = blockIdx.x * blockDim.x + tid; idx < VV * CC * CC;
         idx += gridDim.x * blockDim.x) {
        int og = idx & 3;
        int o4 = (idx >> 2) & 15;
        int c = (idx >> 6) & 63;
        int v = idx >> 12;
        int o = og * 16 + o4;
        float w = 0.f;
        for (int i = 0; i < 3; i++)
            w += s_sh[i * 25 + v] * gw[(i * CC + o) * CC + c];
        g_Wf[idx] = w;
    }
}

// ---------------------------------------------------------------------------
// gemmst: block = (v, n). 512 thr = 16 warps, occupancy 2 (8 warps/SMSP).
// Stage ONCE into smem: x slice xT[n][v] (64KB) + weight slice (16KB).
// Warp = t-chunk tw (16 t); lane = (o4, th). Mainloop per channel:
// 1 LDS.128 weights + 2 LDS.128 x + 16 FFMA2, no global loads.
// Stats fp32-exact via smem atomics; hidden stored fp16 blocked.
// ---------------------------------------------------------------------------
__global__ void __launch_bounds__(512, 2) gemmst(int unused) {
    extern __shared__ float smem[];
    float* xv = smem;                // [64][256]
    float* ws = smem + 16384;        // [64][16][4]
    float* aux = smem + 20480;       // stats[128]
    int tid = threadIdx.x;
    int v = blockIdx.x, n = blockIdx.y;

    if (tid < 128) aux[tid] = 0.f;
    {
        const float4* s4 = (const float4*)(g_xT + ((size_t)n * 25 + v) * 16384);
        float4* d4 = (float4*)xv;
#pragma unroll
        for (int e = 0; e < 8; e++) d4[tid + e * 512] = s4[tid + e * 512];
        const float4* w4 = (const float4*)(g_Wf + (size_t)v * 4096);
        float4* dw = (float4*)ws;
#pragma unroll
        for (int e = 0; e < 2; e++) dw[tid + e * 512] = w4[tid + e * 512];
    }
    __syncthreads();

    int tw = tid >> 5, lane = tid & 31;
    int o4 = lane & 15, th = lane >> 4;

    ull acc[4][4];                   // [og][tp]
#pragma unroll
    for (int og = 0; og < 4; og++) {
        ull b = packrep(g_B[og * 16 + o4]);
#pragma unroll
        for (int tp = 0; tp < 4; tp++) acc[og][tp] = b;
    }

    const float4* wp = (const float4*)ws + o4;                      // + c*16
    const ulonglong2* xp = (const ulonglong2*)xv + tw * 4 + th * 2; // + c*64

#pragma unroll 4
    for (int c = 0; c < CC; c++) {
        float4 w = wp[c * 16];
        ulonglong2 xa = xp[c * 64];
        ulonglong2 xb = xp[c * 64 + 1];
        ull w0 = packrep(w.x), w1 = packrep(w.y);
        ull w2 = packrep(w.z), w3 = packrep(w.w);
        ffma2(acc[0][0], w0, xa.x); ffma2(acc[1][0], w1, xa.x);
        ffma2(acc[2][0], w2, xa.x); ffma2(acc[3][0], w3, xa.x);
        ffma2(acc[0][1], w0, xa.y); ffma2(acc[1][1], w1, xa.y);
        ffma2(acc[2][1], w2, xa.y); ffma2(acc[3][1], w3, xa.y);
        ffma2(acc[0][2], w0, xb.x); ffma2(acc[1][2], w1, xb.x);
        ffma2(acc[2][2], w2, xb.x); ffma2(acc[3][2], w3, xb.x);
        ffma2(acc[0][3], w0, xb.y); ffma2(acc[1][3], w1, xb.y);
        ffma2(acc[2][3], w2, xb.y); ffma2(acc[3][3], w3, xb.y);
    }

    // stats (fp32 exact) + fp16 blocked hidden store
    unsigned* dst = (unsigned*)g_hidh
                    + (((size_t)n * 25 + v) * 16 + tw) * 512 + th * 64 + o4;
#pragma unroll
    for (int og = 0; og < 4; og++) {
        int o = og * 16 + o4;
        float s = 0.f, q = 0.f;
#pragma unroll
        for (int tp = 0; tp < 4; tp++) {
            float h0, h1;
            unpack2(acc[og][tp], h0, h1);
            s += h0 + h1;
            q += h0 * h0 + h1 * h1;
            __half2 hh = __floats2half2_rn(h0, h1);
            dst[og * 128 + tp * 16] = *(unsigned*)&hh;
        }
        atomicAdd(&aux[o], s);
        atomicAdd(&aux[64 + o], q);
    }

    __syncthreads();
    if (tid < 64) atomicAdd(&g_sum[tid], aux[tid]);
    else if (tid < 128) atomicAdd(&g_sumsq[tid - 64], aux[tid]);
}

// ---------------------------------------------------------------------------
// kbn: training-mode biased-var BN folded to per-channel scale/shift.
// ---------------------------------------------------------------------------
__global__ void kbn(const float* __restrict__ gamma, const float* __restrict__ beta) {
    int o = threadIdx.x;
    if (o < CC) {
        float m = g_sum[o] * (1.0f / NPOS);
        float var = g_sumsq[o] * (1.0f / NPOS) - m * m;
        float r = rsqrtf(var + 1e-5f);
        float sc = gamma[o] * r;
        g_scale[o] = sc;
        g_shift[o] = beta[o] - m * sc;
    }
}

// ---------------------------------------------------------------------------
// epi: block = (tw, o-half, n). Phase 1: read blocked fp16 hid (uint2),
// decode into hsm[pos][33]. Phase 2: relu(hid*scale+shift + x), coalesced.
// ---------------------------------------------------------------------------
__global__ void __launch_bounds__(512, 4) epi(const float* __restrict__ x,
                                              float* __restrict__ out) {
    extern __shared__ float hsm[];            // [400][33]
    float* sc_sh = hsm + 400 * HSTR2;
    float* sf_sh = sc_sh + 64;
    int tid = threadIdx.x;
    int tw = blockIdx.x >> 1, h = blockIdx.x & 1;
    int n = blockIdx.y;

    if (tid < 64) { sc_sh[tid] = g_scale[tid]; sf_sh[tid] = g_shift[tid]; }

    const uint2* hb = (const uint2*)g_hidh;
#pragma unroll 2
    for (int i = tid; i < 3200; i += 512) {
        int v = i >> 7, r4 = i & 127;
        uint2 f = hb[(((size_t)n * 25 + v) * 16 + tw) * 256 + h * 128 + r4];
        float2 a = __half22float2(*(const __half2*)&f.x);
        float2 b = __half22float2(*(const __half2*)&f.y);
        int og_l = r4 >> 6;
        int r = r4 & 63;
        int o4e = (r & 7) * 2;
        int tp = (r >> 3) & 3;
        int th = r >> 5;
        int ol = og_l * 16 + o4e;
        int pos = (th * 8 + tp * 2) * 25 + v;
        float* p = hsm + pos * HSTR2 + ol;
        p[0] = a.x;
        p[25 * HSTR2] = a.y;
        p[1] = b.x;
        p[25 * HSTR2 + 1] = b.y;
    }
    __syncthreads();

    if (tid < 400) {
        size_t base = (size_t)n * 409600 + (size_t)h * 32 * 6400 + tw * 400 + tid;
        const float* xp = x + base;
        float* op = out + base;
        const float* hrow = hsm + tid * HSTR2;
#pragma unroll 8
        for (int cl = 0; cl < 32; cl++) {
            int c = h * 32 + cl;
            float val = fmaf(hrow[cl], sc_sh[c], sf_sh[c]) + xp[cl * 6400];
            op[cl * 6400] = fmaxf(val, 0.f);
        }
    }
}

extern "C" void kernel_launch(void* const* d_in, const int* in_sizes, int n_in,
                              void* d_out, int out_size) {
    const float* x     = (const float*)d_in[0];
    const float* A     = (const float*)d_in[1];
    const float* GA    = (const float*)d_in[2];
    const float* gw    = (const float*)d_in[7];
    const float* gb    = (const float*)d_in[8];
    const float* gamma = (const float*)d_in[9];
    const float* beta  = (const float*)d_in[10];
    float* out = (float*)d_out;
    (void)in_sizes; (void)n_in; (void)out_size;

    cudaFuncSetAttribute(ktr, cudaFuncAttributeMaxDynamicSharedMemorySize, KSMEM);
    cudaFuncSetAttribute(gemmst, cudaFuncAttributeMaxDynamicSharedMemorySize, GSMEM);
    cudaFuncSetAttribute(epi, cudaFuncAttributeMaxDynamicSharedMemorySize, ESMEM);

    k0a<<<1, 128>>>(A, GA, gb);                       // idx 0
    ktr<<<1024, 512, KSMEM>>>(x);                     // idx 1
    k0b<<<52, 256>>>(gw);                             // idx 2
    gemmst<<<dim3(VV, NN), 512, GSMEM>>>(0);          // idx 3 -> ncu capture
    kbn<<<1, 64>>>(gamma, beta);                      // idx 4
    epi<<<dim3(32, NN), 512, ESMEM>>>(x, out);        // idx 5
}

// round 16
// speedup vs baseline: 1.3814x; 1.2124x over previous
#include <cuda_runtime.h>
#include <cuda_fp16.h>

#define CC 64
#define TT 256
#define VV 25
#define NN 128
#define NPOS 819200.0f
#define TOTEL 52428800
#define KROW 804                          /* 800 floats data + 4 pad per c-row */
#define KSMEM (16 * KROW * 4)             /* 51456 B -> 4 blocks/SM */
#define GSMEM 46848                       /* Xs 36864 + Wsm 9216 + aux/Bs 768 */
#define HSTR2 33
#define ESMEM ((400 * HSTR2 + 128) * 4)   /* 53312 B */

typedef unsigned int uint;

// Device globals (no runtime allocation)
__device__ __align__(16) __half g_Wh[VV * CC * CC];  // [v][o][c] fp16 folded weights
__device__ __align__(16) float g_B[CC];
__device__ float g_s[75];
__device__ float g_sum[CC];
__device__ float g_sumsq[CC];
__device__ float g_scale[CC];
__device__ float g_shift[CC];
__device__ __align__(16) __half g_xh[TOTEL];         // x fp16: [n][v][t][c]
__device__ __align__(16) __half2 g_hidh[TOTEL / 2];  // hidden fp16: [n][v][o][t/2]

__device__ __forceinline__ uint f2h2(float a, float b) {
    __half2 h = __floats2half2_rn(a, b);
    return *(uint*)&h;
}

// ---------------------------------------------------------------------------
// k0a: softmax rows sum to 1 -> attention collapses to s_i[v] = 1+sum_w(A+GA).
// ---------------------------------------------------------------------------
__global__ void k0a(const float* __restrict__ A, const float* __restrict__ GA,
                    const float* __restrict__ gb) {
    int tid = threadIdx.x;
    if (tid < 75) {
        const float* a = A + tid * 25;
        const float* g = GA + tid * 25;
        float s = 1.f;
        for (int w = 0; w < 25; w++) s += a[w] + g[w];
        g_s[tid] = s;
    }
    if (tid < CC) {
        g_sum[tid] = 0.f;
        g_sumsq[tid] = 0.f;
        float b = 0.f;
        for (int i = 0; i < 3; i++) b += gb[i * CC + tid];
        g_B[tid] = b;
    }
}

// ---------------------------------------------------------------------------
// ktr: x[n][c][t][v] fp32 -> g_xh[n][v][t][c] fp16.
// Tile = 16c x 32t x 25v; smem [16][KROW=804] (800 data + 4 pad), 51.5KB,
// occ 4. Read: coalesced float4 rows (200 float4 per c-row). Write: 2 lanes
// per (t,v) gather 8 c's each (2-way-conflict LDS), pack uint4 (8 halves),
// STG.128 -- full 32B sectors. 200MB read + 100MB write.
// ---------------------------------------------------------------------------
__global__ void __launch_bounds__(512, 4) ktr(const float* __restrict__ x) {
    extern __shared__ float ts[];             // [16][KROW]
    int tid = threadIdx.x;
    int tch = blockIdx.x >> 2, ctile = blockIdx.x & 3;
    int n = blockIdx.y;

    const float4* src4 =
        (const float4*)(x + (size_t)n * 409600 + (size_t)ctile * 16 * 6400 + tch * 800);
    for (int f = tid; f < 3200; f += 512) {
        int c = f / 200, q = f - c * 200;
        ((float4*)(ts + c * KROW))[q] = src4[c * 1600 + q];
    }
    __syncthreads();

    uint4* dst = (uint4*)g_xh;
    for (int e = tid; e < 1600; e += 512) {
        int tv = e >> 1, cq = e & 1;
        const float* p = ts + cq * 8 * KROW + tv;
        uint4 u;
        u.x = f2h2(p[0], p[KROW]);
        u.y = f2h2(p[2 * KROW], p[3 * KROW]);
        u.z = f2h2(p[4 * KROW], p[5 * KROW]);
        u.w = f2h2(p[6 * KROW], p[7 * KROW]);
        int t = tch * 32 + tv / 25;
        int v = tv % 25;
        dst[(((size_t)n * 25 + v) * 256 + t) * 8 + ctile * 2 + cq] = u;
    }
}

// ---------------------------------------------------------------------------
// k0b: fp16 folded weights g_Wh[(v*64+o)*64+c] = half(sum_i s_i[v]*gw[i][o][c]).
// ---------------------------------------------------------------------------
__global__ void k0b(const float* __restrict__ gw) {
    __shared__ float s_sh[75];
    int tid = threadIdx.x;
    if (tid < 75) s_sh[tid] = g_s[tid];
    __syncthreads();
    for (int idx = blockIdx.x * blockDim.x + tid; idx < VV * CC * CC;
         idx += gridDim.x * blockDim.x) {
        int c = idx & 63;
        int o = (idx >> 6) & 63;
        int v = idx >> 12;
        float w = 0.f;
        for (int i = 0; i < 3; i++)
            w += s_sh[i * 25 + v] * gw[(i * CC + o) * CC + c];
        g_Wh[idx] = __float2half(w);
    }
}

// ---------------------------------------------------------------------------
// tcgemm: tensor-core GEMM. Block = (v, n), 512 thr = 16 warps, occ 2.
// H[64o][256t] = W[64o][64c] @ X[64c][256t] via mma.m16n8k16 (fp16 in,
// fp32 accum). Warp (om,tn) owns 16o x 64t. Smem rows padded to 144B
// (36w = 4 mod 32 -> conflict-free ldmatrix). Stats fp32-exact from C
// frags -> smem atomics. Hidden -> smem [o][t2] (pitch 130) -> coalesced
// fp16 store g_hidh[n][v][o][t/2].
// ---------------------------------------------------------------------------
__global__ void __launch_bounds__(512, 2) tcgemm(int unused) {
    extern __shared__ __align__(16) char smraw[];
    __half* Xs = (__half*)smraw;              // [256][72]
    __half* Wsm = (__half*)(smraw + 36864);   // [64][72]
    float* aux = (float*)(smraw + 46080);     // stats[128]
    float* Bs = aux + 128;                    // bias[64]
    uint* hsm2 = (uint*)smraw;                // reused: [64][130]

    int tid = threadIdx.x;
    int v = blockIdx.x, n = blockIdx.y;

    if (tid < 128) aux[tid] = 0.f;
    if (tid < 64) Bs[tid] = g_B[tid];

    // stage X (32KB fp16) and W (8KB fp16), padded rows
    {
        const uint4* xsrc = (const uint4*)(g_xh + ((size_t)n * 25 + v) * 16384);
#pragma unroll
        for (int i = 0; i < 4; i++) {
            int u = tid + i * 512;
            int t = u >> 3, q = u & 7;
            ((uint4*)(Xs + t * 72))[q] = xsrc[u];
        }
        const uint4* wsrc = (const uint4*)(g_Wh + (size_t)v * 4096);
        {
            int o = tid >> 3, q = tid & 7;
            ((uint4*)(Wsm + o * 72))[q] = wsrc[tid];
        }
    }
    __syncthreads();

    int w = tid >> 5, lane = tid & 31;
    int om = w & 3, tn = w >> 2;
    int g = lane >> 2, tig = lane & 3;
    int sub = lane >> 3, lrow = lane & 7;

    uint xs_u = (uint)__cvta_generic_to_shared(Xs);
    uint ws_u = (uint)__cvta_generic_to_shared(Wsm);
    // A: m0 rows g c0-7, m1 rows g+8 c0-7, m2 rows g c8-15, m3 rows g+8 c8-15
    uint aA = ws_u + (om * 16 + (sub & 1) * 8 + lrow) * 144 + (sub >> 1) * 16;
    // B: m0/m1 = t rows lo (k chunks 0,1), m2/m3 = t rows hi
    uint aB = xs_u + (tn * 64 + (sub >> 1) * 8 + lrow) * 144 + (sub & 1) * 16;

    uint A0[4], A1[4], A2[4], A3[4];
#pragma unroll
    for (int k = 0; k < 4; k++)
        asm volatile("ldmatrix.sync.aligned.m8n8.x4.shared.b16 {%0,%1,%2,%3}, [%4];"
                     : "=r"(A0[k]), "=r"(A1[k]), "=r"(A2[k]), "=r"(A3[k])
                     : "r"(aA + k * 32));

    float acc[8][4];
    {
        float blo = Bs[om * 16 + g];
        float bhi = Bs[om * 16 + 8 + g];
#pragma unroll
        for (int j = 0; j < 8; j++) {
            acc[j][0] = blo; acc[j][1] = blo;
            acc[j][2] = bhi; acc[j][3] = bhi;
        }
    }

#pragma unroll
    for (int np = 0; np < 4; np++) {
        uint bbase = aB + np * 2304;          // 16 t-rows * 144B
#pragma unroll
        for (int k = 0; k < 4; k++) {
            uint b0, b1, b2, b3;
            asm volatile("ldmatrix.sync.aligned.m8n8.x4.shared.b16 {%0,%1,%2,%3}, [%4];"
                         : "=r"(b0), "=r"(b1), "=r"(b2), "=r"(b3)
                         : "r"(bbase + k * 32));
            asm volatile(
                "mma.sync.aligned.m16n8k16.row.col.f32.f16.f16.f32 "
                "{%0,%1,%2,%3}, {%4,%5,%6,%7}, {%8,%9}, {%0,%1,%2,%3};"
                : "+f"(acc[2 * np][0]), "+f"(acc[2 * np][1]),
                  "+f"(acc[2 * np][2]), "+f"(acc[2 * np][3])
                : "r"(A0[k]), "r"(A1[k]), "r"(A2[k]), "r"(A3[k]), "r"(b0), "r"(b1));
            asm volatile(
                "mma.sync.aligned.m16n8k16.row.col.f32.f16.f16.f32 "
                "{%0,%1,%2,%3}, {%4,%5,%6,%7}, {%8,%9}, {%0,%1,%2,%3};"
                : "+f"(acc[2 * np + 1][0]), "+f"(acc[2 * np + 1][1]),
                  "+f"(acc[2 * np + 1][2]), "+f"(acc[2 * np + 1][3])
                : "r"(A0[k]), "r"(A1[k]), "r"(A2[k]), "r"(A3[k]), "r"(b2), "r"(b3));
        }
    }

    // fp32-exact stats
    {
        float slo = 0.f, qlo = 0.f, shi = 0.f, qhi = 0.f;
#pragma unroll
        for (int j = 0; j < 8; j++) {
            slo += acc[j][0] + acc[j][1];
            qlo += acc[j][0] * acc[j][0] + acc[j][1] * acc[j][1];
            shi += acc[j][2] + acc[j][3];
            qhi += acc[j][2] * acc[j][2] + acc[j][3] * acc[j][3];
        }
        int olo = om * 16 + g;
        atomicAdd(&aux[olo], slo);
        atomicAdd(&aux[64 + olo], qlo);
        atomicAdd(&aux[olo + 8], shi);
        atomicAdd(&aux[64 + olo + 8], qhi);
    }
    __syncthreads();                          // all ldmatrix reads of Xs done

    // frags -> hsm2[o][t2] (pitch 130)
    {
        int olo = om * 16 + g;
#pragma unroll
        for (int j = 0; j < 8; j++) {
            int col = tn * 32 + j * 4 + tig;
            hsm2[olo * 130 + col] = f2h2(acc[j][0], acc[j][1]);
            hsm2[(olo + 8) * 130 + col] = f2h2(acc[j][2], acc[j][3]);
        }
    }
    __syncthreads();

    // coalesced hidden store + stat merge
    {
        uint2* hdst = (uint2*)g_hidh;
#pragma unroll
        for (int i = 0; i < 8; i++) {
            int idx = tid + i * 512;
            int o = idx >> 6, q = idx & 63;
            uint2 val = *(const uint2*)(hsm2 + o * 130 + 2 * q);
            hdst[(((size_t)n * 25 + v) * 64 + o) * 64 + q] = val;
        }
    }
    if (tid < 64) atomicAdd(&g_sum[tid], aux[tid]);
    else if (tid < 128) atomicAdd(&g_sumsq[tid - 64], aux[tid]);
}

// ---------------------------------------------------------------------------
// kbn: training-mode biased-var BN folded to per-channel scale/shift.
// ---------------------------------------------------------------------------
__global__ void kbn(const float* __restrict__ gamma, const float* __restrict__ beta) {
    int o = threadIdx.x;
    if (o < CC) {
        float m = g_sum[o] * (1.0f / NPOS);
        float var = g_sumsq[o] * (1.0f / NPOS) - m * m;
        float r = rsqrtf(var + 1e-5f);
        float sc = gamma[o] * r;
        g_scale[o] = sc;
        g_shift[o] = beta[o] - m * sc;
    }
}

// ---------------------------------------------------------------------------
// epi: block = (tw of 16 t, o-half h, n). Phase 1: read hid[n][v][o][t2]
// (uint2, full 32B sectors), decode into hsm[pos][33]. Phase 2:
// out = relu(hid*scale+shift + x), fully coalesced. occ 4.
// ---------------------------------------------------------------------------
__global__ void __launch_bounds__(512, 4) epi(const float* __restrict__ x,
                                              float* __restrict__ out) {
    extern __shared__ float hsm[];            // [400][33]
    float* sc_sh = hsm + 400 * HSTR2;
    float* sf_sh = sc_sh + 64;
    int tid = threadIdx.x;
    int tw = blockIdx.x >> 1, h = blockIdx.x & 1;
    int n = blockIdx.y;

    if (tid < 64) { sc_sh[tid] = g_scale[tid]; sf_sh[tid] = g_shift[tid]; }

    const uint2* hb = (const uint2*)g_hidh;
#pragma unroll 2
    for (int i = tid; i < 3200; i += 512) {
        int v = i >> 7, r = i & 127;
        int o_l = r >> 2, t2q = r & 3;
        int o = h * 32 + o_l;
        uint2 u = hb[(((size_t)n * 25 + v) * 64 + o) * 64 + tw * 4 + t2q];
        float2 a = __half22float2(*(const __half2*)&u.x);
        float2 b = __half22float2(*(const __half2*)&u.y);
        float* p = hsm + (t2q * 4 * 25 + v) * HSTR2 + o_l;
        p[0] = a.x;
        p[25 * HSTR2] = a.y;
        p[2 * 25 * HSTR2] = b.x;
        p[3 * 25 * HSTR2] = b.y;
    }
    __syncthreads();

    if (tid < 400) {
        size_t base = (size_t)n * 409600 + (size_t)h * 32 * 6400 + tw * 400 + tid;
        const float* xp = x + base;
        float* op = out + base;
        const float* hrow = hsm + tid * HSTR2;
#pragma unroll 8
        for (int cl = 0; cl < 32; cl++) {
            int c = h * 32 + cl;
            float val = fmaf(hrow[cl], sc_sh[c], sf_sh[c]) + xp[cl * 6400];
            op[cl * 6400] = fmaxf(val, 0.f);
        }
    }
}

extern "C" void kernel_launch(void* const* d_in, const int* in_sizes, int n_in,
                              void* d_out, int out_size) {
    const float* x     = (const float*)d_in[0];
    const float* A     = (const float*)d_in[1];
    const float* GA    = (const float*)d_in[2];
    const float* gw    = (const float*)d_in[7];
    const float* gb    = (const float*)d_in[8];
    const float* gamma = (const float*)d_in[9];
    const float* beta  = (const float*)d_in[10];
    float* out = (float*)d_out;
    (void)in_sizes; (void)n_in; (void)out_size;

    cudaFuncSetAttribute(ktr, cudaFuncAttributeMaxDynamicSharedMemorySize, KSMEM);
    cudaFuncSetAttribute(tcgemm, cudaFuncAttributeMaxDynamicSharedMemorySize, GSMEM);
    cudaFuncSetAttribute(epi, cudaFuncAttributeMaxDynamicSharedMemorySize, ESMEM);

    k0a<<<1, 128>>>(A, GA, gb);                       // idx 0
    ktr<<<dim3(32, NN), 512, KSMEM>>>(x);             // idx 1
    k0b<<<52, 256>>>(gw);                             // idx 2
    tcgemm<<<dim3(VV, NN), 512, GSMEM>>>(0);          // idx 3 -> ncu capture
    kbn<<<1, 64>>>(gamma, beta);                      // idx 4
    epi<<<dim3(32, NN), 512, ESMEM>>>(x, out);        // idx 5
}